// round 14
// baseline (speedup 1.0000x reference)
#include <cuda_runtime.h>
#include <cuda_bf16.h>
#include <mma.h>
#include <math.h>
#include <stdint.h>

using namespace nvcuda;

#define NN 50000
#define DD 256
#define EE 800000
#define LL 3

// ---------------- device scratch ---------------------------------------------
__device__ float g_q[NN * DD];
__device__ float g_k[NN * DD];
__device__ float g_v[NN * DD];
__device__ float g_s[NN * DD];
__device__ __nv_bfloat16 g_ahi[NN * DD];         // layer input, bf16-split
__device__ __nv_bfloat16 g_alo[NN * DD];
__device__ __nv_bfloat16 g_wthi[12 * DD * DD];   // [mat][n][k] transposed + split
__device__ __nv_bfloat16 g_wtlo[12 * DD * DD];
__device__ int   g_src[EE];
__device__ int   g_dst[EE];
__device__ int   g_esrc[EE];
__device__ int   g_deg[NN];
__device__ int   g_off[NN + 1];
__device__ int   g_bsum[256];
__device__ int   g_is64;

// ---------------- cp.async helpers --------------------------------------------
__device__ __forceinline__ void cp_async16(uint32_t dst, const void* src) {
    asm volatile("cp.async.cg.shared.global [%0], [%1], 16;" :: "r"(dst), "l"(src));
}
__device__ __forceinline__ void cp_commit() {
    asm volatile("cp.async.commit_group;" ::: "memory");
}
template <int N>
__device__ __forceinline__ void cp_wait() {
    asm volatile("cp.async.wait_group %0;" :: "n"(N) : "memory");
}

// ---------------- edge-index dtype detection + CSR -----------------------------
__global__ void detect_idx_kernel(const int* __restrict__ ei) {
    if (threadIdx.x == 0 && blockIdx.x == 0) {
        int all_hi_zero = 1;
        for (int j = 0; j < 256; j++)
            if (ei[2 * j + 1] != 0) { all_hi_zero = 0; break; }
        g_is64 = all_hi_zero;
    }
}
__global__ void zero_deg_kernel() {
    int i = blockIdx.x * blockDim.x + threadIdx.x;
    if (i < NN) g_deg[i] = 0;
}
__global__ void convert_hist_kernel(const int* __restrict__ ei) {
    int i = blockIdx.x * blockDim.x + threadIdx.x;
    if (i >= EE) return;
    int s, d;
    if (g_is64) { s = ei[2 * i]; d = ei[2 * (EE + i)]; }
    else        { s = ei[i];     d = ei[EE + i]; }
    g_src[i] = s; g_dst[i] = d;
    atomicAdd(&g_deg[d], 1);
}
#define SCAN_NB 196
__global__ __launch_bounds__(256) void scan1_kernel() {
    __shared__ int sh[256];
    int i = blockIdx.x * 256 + threadIdx.x;
    int v = (i < NN) ? g_deg[i] : 0;
    sh[threadIdx.x] = v;
    __syncthreads();
    for (int o = 128; o; o >>= 1) {
        if (threadIdx.x < o) sh[threadIdx.x] += sh[threadIdx.x + o];
        __syncthreads();
    }
    if (threadIdx.x == 0) g_bsum[blockIdx.x] = sh[0];
}
__global__ __launch_bounds__(256) void scan2_kernel() {
    __shared__ int sh[256];
    int t = threadIdx.x;
    sh[t] = (t < SCAN_NB) ? g_bsum[t] : 0;
    __syncthreads();
    for (int o = 1; o < 256; o <<= 1) {
        int v = (t >= o) ? sh[t - o] : 0;
        __syncthreads();
        sh[t] += v;
        __syncthreads();
    }
    if (t < SCAN_NB) g_bsum[t] = (t == 0) ? 0 : sh[t - 1];
    if (t == 0) g_off[NN] = EE;
}
__global__ __launch_bounds__(256) void scan3_kernel() {
    __shared__ int sh[256];
    int i = blockIdx.x * 256 + threadIdx.x;
    int t = threadIdx.x;
    int v = (i < NN) ? g_deg[i] : 0;
    sh[t] = v;
    __syncthreads();
    for (int o = 1; o < 256; o <<= 1) {
        int u = (t >= o) ? sh[t - o] : 0;
        __syncthreads();
        sh[t] += u;
        __syncthreads();
    }
    if (i < NN) {
        g_off[i] = g_bsum[blockIdx.x] + sh[t] - v;
        g_deg[i] = 0;
    }
}
__global__ void scatter_kernel() {
    int i = blockIdx.x * blockDim.x + threadIdx.x;
    if (i >= EE) return;
    int d = g_dst[i];
    int pos = g_off[d] + atomicAdd(&g_deg[d], 1);
    g_esrc[pos] = g_src[i];
}

// ---------------- weight transpose + bf16 split --------------------------------
__global__ __launch_bounds__(256) void wsplit_kernel(
    const float* __restrict__ Wq, const float* __restrict__ Wk,
    const float* __restrict__ Wv, const float* __restrict__ Ws)
{
    __shared__ float t[32][33];
    int m = blockIdx.z;
    int l = m >> 2, wi = m & 3;
    const float* W = ((wi == 0) ? Wq : (wi == 1) ? Wk : (wi == 2) ? Wv : Ws) + (size_t)l * DD * DD;
    int k0 = blockIdx.y * 32, n0 = blockIdx.x * 32;
    #pragma unroll
    for (int r = 0; r < 32; r += 8) {
        int k = k0 + threadIdx.y + r, n = n0 + threadIdx.x;
        t[threadIdx.y + r][threadIdx.x] = W[k * DD + n];
    }
    __syncthreads();
    __nv_bfloat16* ohi = g_wthi + (size_t)m * DD * DD;
    __nv_bfloat16* olo = g_wtlo + (size_t)m * DD * DD;
    #pragma unroll
    for (int r = 0; r < 32; r += 8) {
        int n = n0 + threadIdx.y + r, k = k0 + threadIdx.x;
        float x = t[threadIdx.x][threadIdx.y + r];
        __nv_bfloat16 hi = __float2bfloat16(x);
        __nv_bfloat16 lo = __float2bfloat16(x - __bfloat162float(hi));
        ohi[n * DD + k] = hi;
        olo[n * DD + k] = lo;
    }
}

// ---------------- A split for the layer-0 input x ------------------------------
__global__ __launch_bounds__(256) void asplit_kernel(const float* __restrict__ A) {
    int i = blockIdx.x * blockDim.x + threadIdx.x;   // float4 index
    if (i >= NN * DD / 4) return;
    float4 av = __ldg((const float4*)A + i);
    __nv_bfloat16 h0 = __float2bfloat16(av.x);
    __nv_bfloat16 h1 = __float2bfloat16(av.y);
    __nv_bfloat16 h2 = __float2bfloat16(av.z);
    __nv_bfloat16 h3 = __float2bfloat16(av.w);
    __nv_bfloat162 hl = __halves2bfloat162(h0, h1);
    __nv_bfloat162 hh = __halves2bfloat162(h2, h3);
    __nv_bfloat162 ll = __halves2bfloat162(
        __float2bfloat16(av.x - __bfloat162float(h0)),
        __float2bfloat16(av.y - __bfloat162float(h1)));
    __nv_bfloat162 lh = __halves2bfloat162(
        __float2bfloat16(av.z - __bfloat162float(h2)),
        __float2bfloat16(av.w - __bfloat162float(h3)));
    ((__nv_bfloat162*)g_ahi)[i * 2]     = hl;
    ((__nv_bfloat162*)g_ahi)[i * 2 + 1] = hh;
    ((__nv_bfloat162*)g_alo)[i * 2]     = ll;
    ((__nv_bfloat162*)g_alo)[i * 2 + 1] = lh;
}

// ---------------- bf16x3 WMMA GEMM: CTA 128x256, 512 threads -------------------
// 16 warps, warp tile 64x32. BK=32, 2-stage cp.async. blockIdx.z = {q,k,v,s}.
#define APITCH 40                        // bf16 elems; 80B pitch (16B-aligned rows)
#define OFF_AHI 0
#define OFF_ALO 10240                    // 128*40*2
#define OFF_BHI 20480
#define OFF_BLO 40960                    // Bhi 256*40*2 = 20480
#define STAGE_B 61440
#define GEMM_SMEM (2 * STAGE_B)          // 122880 -> 1 CTA/SM, 16 warps

__global__ __launch_bounds__(512, 1) void bf16x3_gemm_kernel(
    int layer,
    const float* __restrict__ bq, const float* __restrict__ bk,
    const float* __restrict__ bv, const float* __restrict__ bs, int M)
{
    extern __shared__ char smem[];
    const int tid = threadIdx.x;
    const int wid = tid >> 5;
    const int wm = wid >> 3;          // 0..1  (64-row half)
    const int wn = wid & 7;           // 0..7  (32-col slice)
    const int bm = blockIdx.x * 128;
    const int z  = blockIdx.z;

    const int mat = layer * 4 + z;
    const __nv_bfloat16* Whi = g_wthi + (size_t)mat * DD * DD;
    const __nv_bfloat16* Wlo = g_wtlo + (size_t)mat * DD * DD;

    const uint32_t smem_base = (uint32_t)__cvta_generic_to_shared(smem);

    wmma::fragment<wmma::accumulator, 16, 16, 16, float> c[4][2];
    #pragma unroll
    for (int i = 0; i < 4; i++)
        #pragma unroll
        for (int j = 0; j < 2; j++) wmma::fill_fragment(c[i][j], 0.f);

    // 3072 16B segs per chunk / 512 threads = 6 cp.async each.
    auto load_chunk = [&](int ck, int buf) {
        uint32_t sb = smem_base + buf * STAGE_B;
        #pragma unroll
        for (int it = 0; it < 6; it++) {
            int seg = tid + it * 512;          // 0..3071
            const __nv_bfloat16* gp;
            uint32_t daddr;
            if (seg < 1024) {                  // A: hi (0..511), lo (512..1023)
                int split = seg >> 9;
                int rem = seg & 511;
                int row = rem >> 2;
                int s4  = rem & 3;
                daddr = sb + (split ? OFF_ALO : OFF_AHI) + (row * APITCH + s4 * 8) * 2;
                int gr = min(bm + row, M - 1);
                gp = (split ? g_alo : g_ahi) + (size_t)gr * DD + ck * 32 + s4 * 8;
            } else {                           // B: hi (0..1023), lo (1024..2047)
                int seg2 = seg - 1024;
                int split = seg2 >> 10;
                int rem = seg2 & 1023;
                int row = rem >> 2;            // 0..255
                int s4  = rem & 3;
                daddr = sb + (split ? OFF_BLO : OFF_BHI) + (row * APITCH + s4 * 8) * 2;
                gp = (split ? Wlo : Whi) + (size_t)row * DD + ck * 32 + s4 * 8;
            }
            cp_async16(daddr, gp);
        }
        cp_commit();
    };

    load_chunk(0, 0);

    for (int ck = 0; ck < 8; ck++) {
        if (ck < 7) { load_chunk(ck + 1, (ck + 1) & 1); cp_wait<1>(); }
        else { cp_wait<0>(); }
        __syncthreads();

        char* stg = smem + (ck & 1) * STAGE_B;
        __nv_bfloat16* Ahi = (__nv_bfloat16*)(stg + OFF_AHI);
        __nv_bfloat16* Alo = (__nv_bfloat16*)(stg + OFF_ALO);
        __nv_bfloat16* Bhi = (__nv_bfloat16*)(stg + OFF_BHI);
        __nv_bfloat16* Blo = (__nv_bfloat16*)(stg + OFF_BLO);

        #pragma unroll
        for (int kk = 0; kk < 2; kk++) {
            // cache B fragments for this warp's 32-col slice (hi + lo)
            wmma::fragment<wmma::matrix_b, 16, 16, 16, __nv_bfloat16, wmma::col_major> bH[2], bL[2];
            #pragma unroll
            for (int j = 0; j < 2; j++) {
                wmma::load_matrix_sync(bH[j], Bhi + (wn * 32 + j * 16) * APITCH + kk * 16, APITCH);
                wmma::load_matrix_sync(bL[j], Blo + (wn * 32 + j * 16) * APITCH + kk * 16, APITCH);
            }
            // stream A-hi fragments one at a time: hi*hi + hi*lo
            #pragma unroll
            for (int i = 0; i < 4; i++) {
                wmma::fragment<wmma::matrix_a, 16, 16, 16, __nv_bfloat16, wmma::row_major> a;
                wmma::load_matrix_sync(a, Ahi + (wm * 64 + i * 16) * APITCH + kk * 16, APITCH);
                #pragma unroll
                for (int j = 0; j < 2; j++) {
                    wmma::mma_sync(c[i][j], a, bH[j], c[i][j]);
                    wmma::mma_sync(c[i][j], a, bL[j], c[i][j]);
                }
            }
            // stream A-lo fragments: lo*hi
            #pragma unroll
            for (int i = 0; i < 4; i++) {
                wmma::fragment<wmma::matrix_a, 16, 16, 16, __nv_bfloat16, wmma::row_major> a;
                wmma::load_matrix_sync(a, Alo + (wm * 64 + i * 16) * APITCH + kk * 16, APITCH);
                #pragma unroll
                for (int j = 0; j < 2; j++)
                    wmma::mma_sync(c[i][j], a, bH[j], c[i][j]);
            }
        }
        __syncthreads();
    }

    // epilogue: two N=128 halves staged through smem, coalesced store + bias
    const float* bias = ((z == 0) ? bq : (z == 1) ? bk : (z == 2) ? bv : bs);
    float* outp = (z == 0) ? g_q : (z == 1) ? g_k : (z == 2) ? g_v : g_s;
    float* stage = (float*)smem;   // 128 x 132 floats = 67584B <= GEMM_SMEM

    #pragma unroll
    for (int h = 0; h < 2; h++) {
        if ((wn >> 2) == h) {
            #pragma unroll
            for (int i = 0; i < 4; i++)
                #pragma unroll
                for (int j = 0; j < 2; j++)
                    wmma::store_matrix_sync(
                        stage + (wm * 64 + i * 16) * 132 + (wn & 3) * 32 + j * 16,
                        c[i][j], 132, wmma::mem_row_major);
        }
        __syncthreads();
        #pragma unroll
        for (int it = 0; it < 8; it++) {
            int idx = tid + it * 512;           // 0..4095 float4s
            int row = idx >> 5, c4 = idx & 31;
            int gr = bm + row;
            if (gr < M) {
                float4 vv = *(float4*)(stage + row * 132 + c4 * 4);
                float4 bb = __ldg((const float4*)(bias + h * 128 + c4 * 4));
                vv.x += bb.x; vv.y += bb.y; vv.z += bb.z; vv.w += bb.w;
                *(float4*)(outp + (size_t)gr * DD + h * 128 + c4 * 4) = vv;
            }
        }
        __syncthreads();
    }
}

// ---------------- fused per-destination attention ------------------------------
__device__ __forceinline__ float warp_dot_qk(float4 qa, float4 qb, int s, int lane) {
    const float4* k4 = (const float4*)(g_k + (size_t)s * DD);
    float4 ka = __ldg(&k4[lane]);
    float4 kb = __ldg(&k4[lane + 32]);
    float p = qa.x * ka.x + qa.y * ka.y + qa.z * ka.z + qa.w * ka.w
            + qb.x * kb.x + qb.y * kb.y + qb.z * kb.z + qb.w * kb.w;
    #pragma unroll
    for (int o = 16; o; o >>= 1) p += __shfl_xor_sync(0xffffffffu, p, o);
    return p * 0.0625f;
}

__device__ __forceinline__ void store_split4(int d, int col0, float4 r) {
    __nv_bfloat16 h0 = __float2bfloat16(r.x);
    __nv_bfloat16 h1 = __float2bfloat16(r.y);
    __nv_bfloat16 h2 = __float2bfloat16(r.z);
    __nv_bfloat16 h3 = __float2bfloat16(r.w);
    __nv_bfloat162* dh = (__nv_bfloat162*)(g_ahi + (size_t)d * DD + col0);
    dh[0] = __halves2bfloat162(h0, h1);
    dh[1] = __halves2bfloat162(h2, h3);
    __nv_bfloat162* dl = (__nv_bfloat162*)(g_alo + (size_t)d * DD + col0);
    dl[0] = __halves2bfloat162(__float2bfloat16(r.x - __bfloat162float(h0)),
                               __float2bfloat16(r.y - __bfloat162float(h1)));
    dl[1] = __halves2bfloat162(__float2bfloat16(r.z - __bfloat162float(h2)),
                               __float2bfloat16(r.w - __bfloat162float(h3)));
}

// mode 1: intermediate layer -> relu + bf16 split store; mode 0: final -> fp32 out
__global__ __launch_bounds__(256) void dst_attn_kernel(float* __restrict__ out, int mode) {
    int d = (blockIdx.x * blockDim.x + threadIdx.x) >> 5;
    int lane = threadIdx.x & 31;
    if (d >= NN) return;

    int beg = g_off[d];
    int deg = g_off[d + 1] - beg;

    const float4* q4 = (const float4*)(g_q + (size_t)d * DD);
    float4 qa = q4[lane], qb = q4[lane + 32];

    float ar0 = 0.f, ar1 = 0.f, ar2 = 0.f, ar3 = 0.f;
    float mx = -INFINITY;
    bool small = (deg <= 128);

    for (int j = 0; j < deg; j++) {
        int s = __ldg(&g_esrc[beg + j]);
        float p = warp_dot_qk(qa, qb, s, lane);
        mx = fmaxf(mx, p);
        if (small && ((j & 31) == lane)) {
            int slot = j >> 5;
            if      (slot == 0) ar0 = p;
            else if (slot == 1) ar1 = p;
            else if (slot == 2) ar2 = p;
            else                ar3 = p;
        }
    }

    float den = 0.f;
    if (small) {
        int t = 0;
        for (int j = lane; j < deg; j += 32, t++) {
            float a = (t == 0) ? ar0 : (t == 1) ? ar1 : (t == 2) ? ar2 : ar3;
            den += __expf(a - mx);
        }
        #pragma unroll
        for (int o = 16; o; o >>= 1) den += __shfl_xor_sync(0xffffffffu, den, o);
    } else {
        for (int j = 0; j < deg; j++) {
            int s = __ldg(&g_esrc[beg + j]);
            float p = warp_dot_qk(qa, qb, s, lane);
            den += (lane == 0) ? __expf(p - mx) : 0.f;
        }
        den = __shfl_sync(0xffffffffu, den, 0);
    }
    float invden = 1.0f / (den + 1e-16f);

    float4 acca = make_float4(0.f, 0.f, 0.f, 0.f);
    float4 accb = make_float4(0.f, 0.f, 0.f, 0.f);
    for (int j = 0; j < deg; j++) {
        float a;
        if (small) {
            int slot = j >> 5;
            float av = (slot == 0) ? ar0 : (slot == 1) ? ar1 : (slot == 2) ? ar2 : ar3;
            a = __shfl_sync(0xffffffffu, av, j & 31);
        } else {
            int s0 = __ldg(&g_esrc[beg + j]);
            a = warp_dot_qk(qa, qb, s0, lane);
        }
        float attn = __expf(a - mx) * invden;
        int s = __ldg(&g_esrc[beg + j]);
        const float4* v4 = (const float4*)(g_v + (size_t)s * DD);
        float4 va = __ldg(&v4[lane]);
        float4 vb = __ldg(&v4[lane + 32]);
        acca.x += attn * va.x; acca.y += attn * va.y;
        acca.z += attn * va.z; acca.w += attn * va.w;
        accb.x += attn * vb.x; accb.y += attn * vb.y;
        accb.z += attn * vb.z; accb.w += attn * vb.w;
    }

    const float4* s4 = (const float4*)(g_s + (size_t)d * DD);
    float4 sa = s4[lane], sb = s4[lane + 32];
    float4 oa, ob;
    oa.x = acca.x + sa.x; oa.y = acca.y + sa.y;
    oa.z = acca.z + sa.z; oa.w = acca.w + sa.w;
    ob.x = accb.x + sb.x; ob.y = accb.y + sb.y;
    ob.z = accb.z + sb.z; ob.w = accb.w + sb.w;

    if (mode) {
        oa.x = fmaxf(oa.x, 0.f); oa.y = fmaxf(oa.y, 0.f);
        oa.z = fmaxf(oa.z, 0.f); oa.w = fmaxf(oa.w, 0.f);
        ob.x = fmaxf(ob.x, 0.f); ob.y = fmaxf(ob.y, 0.f);
        ob.z = fmaxf(ob.z, 0.f); ob.w = fmaxf(ob.w, 0.f);
        store_split4(d, lane * 4, oa);
        store_split4(d, 128 + lane * 4, ob);
    } else {
        float4* o4 = (float4*)(out + (size_t)d * DD);
        o4[lane] = oa;
        o4[lane + 32] = ob;
    }
}

// ---------------- launch --------------------------------------------------------
extern "C" void kernel_launch(void* const* d_in, const int* in_sizes, int n_in,
                              void* d_out, int out_size) {
    const float* x  = (const float*)d_in[0];
    const int*   ei = (const int*)d_in[1];
    const float* Wq = (const float*)d_in[2];
    const float* bq = (const float*)d_in[3];
    const float* Wk = (const float*)d_in[4];
    const float* bk = (const float*)d_in[5];
    const float* Wv = (const float*)d_in[6];
    const float* bv = (const float*)d_in[7];
    const float* Ws = (const float*)d_in[8];
    const float* bs = (const float*)d_in[9];
    float* out = (float*)d_out;

    cudaFuncSetAttribute(bf16x3_gemm_kernel,
                         cudaFuncAttributeMaxDynamicSharedMemorySize, GEMM_SMEM);

    int split_blocks = (NN * DD / 4 + 255) / 256;
    asplit_kernel<<<split_blocks, 256>>>(x);            // layer-0 input split
    wsplit_kernel<<<dim3(8, 8, 12), dim3(32, 8)>>>(Wq, Wk, Wv, Ws);

    detect_idx_kernel<<<1, 32>>>(ei);
    zero_deg_kernel<<<(NN + 255) / 256, 256>>>();
    convert_hist_kernel<<<(EE + 255) / 256, 256>>>(ei);
    scan1_kernel<<<SCAN_NB, 256>>>();
    scan2_kernel<<<1, 256>>>();
    scan3_kernel<<<SCAN_NB, 256>>>();
    scatter_kernel<<<(EE + 255) / 256, 256>>>();

    dim3 ggrid((NN + 127) / 128, 1, 4);
    int attn_blocks = (NN * 32 + 255) / 256;

    for (int l = 0; l < LL; l++) {
        size_t bo = (size_t)l * DD;
        bf16x3_gemm_kernel<<<ggrid, 512, GEMM_SMEM>>>(
            l, bq + bo, bk + bo, bv + bo, bs + bo, NN);
        dst_attn_kernel<<<attn_blocks, 256>>>(out, (l < LL - 1) ? 1 : 0);
    }
}

// round 16
// speedup vs baseline: 1.0928x; 1.0928x over previous
#include <cuda_runtime.h>
#include <cuda_bf16.h>
#include <mma.h>
#include <math.h>
#include <stdint.h>

using namespace nvcuda;

#define NN 50000
#define DD 256
#define EE 800000
#define LL 3

// ---------------- device scratch ---------------------------------------------
__device__ float g_q[NN * DD];
__device__ float g_k[NN * DD];
__device__ float g_v[NN * DD];
__device__ float g_s[NN * DD];
__device__ __nv_bfloat16 g_ahi[NN * DD];         // layer input, bf16-split
__device__ __nv_bfloat16 g_alo[NN * DD];
__device__ __nv_bfloat16 g_wthi[12 * DD * DD];   // [mat][n][k] transposed + split
__device__ __nv_bfloat16 g_wtlo[12 * DD * DD];
__device__ int   g_src[EE];
__device__ int   g_dst[EE];
__device__ int   g_esrc[EE];
__device__ int   g_deg[NN];
__device__ int   g_off[NN + 1];
__device__ int   g_bsum[256];
__device__ int   g_is64;

// ---------------- cp.async helpers --------------------------------------------
__device__ __forceinline__ void cp_async16(uint32_t dst, const void* src) {
    asm volatile("cp.async.cg.shared.global [%0], [%1], 16;" :: "r"(dst), "l"(src));
}
__device__ __forceinline__ void cp_commit() {
    asm volatile("cp.async.commit_group;" ::: "memory");
}
template <int N>
__device__ __forceinline__ void cp_wait() {
    asm volatile("cp.async.wait_group %0;" :: "n"(N) : "memory");
}

// ---------------- edge-index dtype detection + CSR -----------------------------
__global__ void detect_idx_kernel(const int* __restrict__ ei) {
    if (threadIdx.x == 0 && blockIdx.x == 0) {
        int all_hi_zero = 1;
        for (int j = 0; j < 256; j++)
            if (ei[2 * j + 1] != 0) { all_hi_zero = 0; break; }
        g_is64 = all_hi_zero;
    }
}
__global__ void zero_deg_kernel() {
    int i = blockIdx.x * blockDim.x + threadIdx.x;
    if (i < NN) g_deg[i] = 0;
}
__global__ void convert_hist_kernel(const int* __restrict__ ei) {
    int i = blockIdx.x * blockDim.x + threadIdx.x;
    if (i >= EE) return;
    int s, d;
    if (g_is64) { s = ei[2 * i]; d = ei[2 * (EE + i)]; }
    else        { s = ei[i];     d = ei[EE + i]; }
    g_src[i] = s; g_dst[i] = d;
    atomicAdd(&g_deg[d], 1);
}
#define SCAN_NB 196
__global__ __launch_bounds__(256) void scan1_kernel() {
    __shared__ int sh[256];
    int i = blockIdx.x * 256 + threadIdx.x;
    int v = (i < NN) ? g_deg[i] : 0;
    sh[threadIdx.x] = v;
    __syncthreads();
    for (int o = 128; o; o >>= 1) {
        if (threadIdx.x < o) sh[threadIdx.x] += sh[threadIdx.x + o];
        __syncthreads();
    }
    if (threadIdx.x == 0) g_bsum[blockIdx.x] = sh[0];
}
__global__ __launch_bounds__(256) void scan2_kernel() {
    __shared__ int sh[256];
    int t = threadIdx.x;
    sh[t] = (t < SCAN_NB) ? g_bsum[t] : 0;
    __syncthreads();
    for (int o = 1; o < 256; o <<= 1) {
        int v = (t >= o) ? sh[t - o] : 0;
        __syncthreads();
        sh[t] += v;
        __syncthreads();
    }
    if (t < SCAN_NB) g_bsum[t] = (t == 0) ? 0 : sh[t - 1];
    if (t == 0) g_off[NN] = EE;
}
__global__ __launch_bounds__(256) void scan3_kernel() {
    __shared__ int sh[256];
    int i = blockIdx.x * 256 + threadIdx.x;
    int t = threadIdx.x;
    int v = (i < NN) ? g_deg[i] : 0;
    sh[t] = v;
    __syncthreads();
    for (int o = 1; o < 256; o <<= 1) {
        int u = (t >= o) ? sh[t - o] : 0;
        __syncthreads();
        sh[t] += u;
        __syncthreads();
    }
    if (i < NN) {
        g_off[i] = g_bsum[blockIdx.x] + sh[t] - v;
        g_deg[i] = 0;
    }
}
__global__ void scatter_kernel() {
    int i = blockIdx.x * blockDim.x + threadIdx.x;
    if (i >= EE) return;
    int d = g_dst[i];
    int pos = g_off[d] + atomicAdd(&g_deg[d], 1);
    g_esrc[pos] = g_src[i];
}

// ---------------- weight transpose + bf16 split --------------------------------
__global__ __launch_bounds__(256) void wsplit_kernel(
    const float* __restrict__ Wq, const float* __restrict__ Wk,
    const float* __restrict__ Wv, const float* __restrict__ Ws)
{
    __shared__ float t[32][33];
    int m = blockIdx.z;
    int l = m >> 2, wi = m & 3;
    const float* W = ((wi == 0) ? Wq : (wi == 1) ? Wk : (wi == 2) ? Wv : Ws) + (size_t)l * DD * DD;
    int k0 = blockIdx.y * 32, n0 = blockIdx.x * 32;
    #pragma unroll
    for (int r = 0; r < 32; r += 8) {
        int k = k0 + threadIdx.y + r, n = n0 + threadIdx.x;
        t[threadIdx.y + r][threadIdx.x] = W[k * DD + n];
    }
    __syncthreads();
    __nv_bfloat16* ohi = g_wthi + (size_t)m * DD * DD;
    __nv_bfloat16* olo = g_wtlo + (size_t)m * DD * DD;
    #pragma unroll
    for (int r = 0; r < 32; r += 8) {
        int n = n0 + threadIdx.y + r, k = k0 + threadIdx.x;
        float x = t[threadIdx.x][threadIdx.y + r];
        __nv_bfloat16 hi = __float2bfloat16(x);
        __nv_bfloat16 lo = __float2bfloat16(x - __bfloat162float(hi));
        ohi[n * DD + k] = hi;
        olo[n * DD + k] = lo;
    }
}

// ---------------- A split for the layer-0 input x ------------------------------
__global__ __launch_bounds__(256) void asplit_kernel(const float* __restrict__ A) {
    int i = blockIdx.x * blockDim.x + threadIdx.x;   // float4 index
    if (i >= NN * DD / 4) return;
    float4 av = __ldg((const float4*)A + i);
    __nv_bfloat16 h0 = __float2bfloat16(av.x);
    __nv_bfloat16 h1 = __float2bfloat16(av.y);
    __nv_bfloat16 h2 = __float2bfloat16(av.z);
    __nv_bfloat16 h3 = __float2bfloat16(av.w);
    __nv_bfloat162 hl = __halves2bfloat162(h0, h1);
    __nv_bfloat162 hh = __halves2bfloat162(h2, h3);
    __nv_bfloat162 ll = __halves2bfloat162(
        __float2bfloat16(av.x - __bfloat162float(h0)),
        __float2bfloat16(av.y - __bfloat162float(h1)));
    __nv_bfloat162 lh = __halves2bfloat162(
        __float2bfloat16(av.z - __bfloat162float(h2)),
        __float2bfloat16(av.w - __bfloat162float(h3)));
    ((__nv_bfloat162*)g_ahi)[i * 2]     = hl;
    ((__nv_bfloat162*)g_ahi)[i * 2 + 1] = hh;
    ((__nv_bfloat162*)g_alo)[i * 2]     = ll;
    ((__nv_bfloat162*)g_alo)[i * 2 + 1] = lh;
}

// ---------------- bf16x3 WMMA GEMM (R11 config: 128x128, 2 CTA/SM) -------------
#define APITCH 40                       // bf16 elems; 80B pitch (16B-aligned rows)
#define TILE_SPLIT_B (128 * APITCH * 2) // 10240 bytes per split
#define STAGE_B (4 * TILE_SPLIT_B)      // 40960
#define GEMM_SMEM (2 * STAGE_B)         // 81920 -> 2 CTAs/SM

__global__ __launch_bounds__(256, 2) void bf16x3_gemm_kernel(
    int layer,
    const float* __restrict__ bq, const float* __restrict__ bk,
    const float* __restrict__ bv, const float* __restrict__ bs, int M)
{
    extern __shared__ char smem[];
    const int tid = threadIdx.x;
    const int wid = tid >> 5;
    const int wm = wid >> 2;          // 0..1
    const int wn = wid & 3;           // 0..3
    const int bm = blockIdx.x * 128;
    const int bn = blockIdx.y * 128;
    const int z  = blockIdx.z;

    const int mat = layer * 4 + z;
    const __nv_bfloat16* Whi = g_wthi + (size_t)mat * DD * DD;
    const __nv_bfloat16* Wlo = g_wtlo + (size_t)mat * DD * DD;

    const uint32_t smem_base = (uint32_t)__cvta_generic_to_shared(smem);

    wmma::fragment<wmma::accumulator, 16, 16, 16, float> c[4][2];
    #pragma unroll
    for (int i = 0; i < 4; i++)
        #pragma unroll
        for (int j = 0; j < 2; j++) wmma::fill_fragment(c[i][j], 0.f);

    auto load_chunk = [&](int ck, int buf) {
        uint32_t sb = smem_base + buf * STAGE_B;
        #pragma unroll
        for (int it = 0; it < 8; it++) {
            int seg = tid + it * 256;          // 0..2047
            int split = seg >> 9;              // 0=Ahi 1=Alo 2=Bhi 3=Blo
            int rem = seg & 511;
            int row = rem >> 2;                // 0..127
            int s4  = rem & 3;                 // 16B seg within 64B row
            uint32_t daddr = sb + split * TILE_SPLIT_B + (row * APITCH + s4 * 8) * 2;
            const __nv_bfloat16* gp;
            if (split == 0) {
                int gr = min(bm + row, M - 1);
                gp = g_ahi + (size_t)gr * DD + ck * 32 + s4 * 8;
            } else if (split == 1) {
                int gr = min(bm + row, M - 1);
                gp = g_alo + (size_t)gr * DD + ck * 32 + s4 * 8;
            } else if (split == 2) {
                gp = Whi + (size_t)(bn + row) * DD + ck * 32 + s4 * 8;
            } else {
                gp = Wlo + (size_t)(bn + row) * DD + ck * 32 + s4 * 8;
            }
            cp_async16(daddr, gp);
        }
        cp_commit();
    };

    load_chunk(0, 0);

    for (int ck = 0; ck < 8; ck++) {
        if (ck < 7) { load_chunk(ck + 1, (ck + 1) & 1); cp_wait<1>(); }
        else { cp_wait<0>(); }
        __syncthreads();

        char* stg = smem + (ck & 1) * STAGE_B;
        __nv_bfloat16* Ahi = (__nv_bfloat16*)(stg);
        __nv_bfloat16* Alo = (__nv_bfloat16*)(stg + TILE_SPLIT_B);
        __nv_bfloat16* Bhi = (__nv_bfloat16*)(stg + 2 * TILE_SPLIT_B);
        __nv_bfloat16* Blo = (__nv_bfloat16*)(stg + 3 * TILE_SPLIT_B);

        #pragma unroll
        for (int kk = 0; kk < 2; kk++) {
            wmma::fragment<wmma::matrix_b, 16, 16, 16, __nv_bfloat16, wmma::col_major> bH[2], bL[2];
            #pragma unroll
            for (int j = 0; j < 2; j++) {
                wmma::load_matrix_sync(bH[j], Bhi + (wn * 32 + j * 16) * APITCH + kk * 16, APITCH);
                wmma::load_matrix_sync(bL[j], Blo + (wn * 32 + j * 16) * APITCH + kk * 16, APITCH);
            }
            {
                wmma::fragment<wmma::matrix_a, 16, 16, 16, __nv_bfloat16, wmma::row_major> aH[4];
                #pragma unroll
                for (int i = 0; i < 4; i++)
                    wmma::load_matrix_sync(aH[i], Ahi + (wm * 64 + i * 16) * APITCH + kk * 16, APITCH);
                #pragma unroll
                for (int i = 0; i < 4; i++)
                    #pragma unroll
                    for (int j = 0; j < 2; j++) {
                        wmma::mma_sync(c[i][j], aH[i], bH[j], c[i][j]);
                        wmma::mma_sync(c[i][j], aH[i], bL[j], c[i][j]);
                    }
            }
            {
                wmma::fragment<wmma::matrix_a, 16, 16, 16, __nv_bfloat16, wmma::row_major> aL[4];
                #pragma unroll
                for (int i = 0; i < 4; i++)
                    wmma::load_matrix_sync(aL[i], Alo + (wm * 64 + i * 16) * APITCH + kk * 16, APITCH);
                #pragma unroll
                for (int i = 0; i < 4; i++)
                    #pragma unroll
                    for (int j = 0; j < 2; j++)
                        wmma::mma_sync(c[i][j], aL[i], bH[j], c[i][j]);
            }
        }
        __syncthreads();
    }

    // epilogue: stage accumulators, coalesced store + bias
    float* stage = (float*)smem;   // 128 x 132
    #pragma unroll
    for (int i = 0; i < 4; i++)
        #pragma unroll
        for (int j = 0; j < 2; j++)
            wmma::store_matrix_sync(stage + (wm * 64 + i * 16) * 132 + wn * 32 + j * 16,
                                    c[i][j], 132, wmma::mem_row_major);
    __syncthreads();

    const float* bias = ((z == 0) ? bq : (z == 1) ? bk : (z == 2) ? bv : bs);
    float* outp = (z == 0) ? g_q : (z == 1) ? g_k : (z == 2) ? g_v : g_s;

    #pragma unroll
    for (int it = 0; it < 16; it++) {
        int idx = tid + it * 256;
        int row = idx >> 5, c4 = idx & 31;
        int gr = bm + row;
        if (gr < M) {
            float4 vv = *(float4*)(stage + row * 132 + c4 * 4);
            float4 bb = __ldg((const float4*)(bias + bn + c4 * 4));
            vv.x += bb.x; vv.y += bb.y; vv.z += bb.z; vv.w += bb.w;
            *(float4*)(outp + (size_t)gr * DD + bn + c4 * 4) = vv;
        }
    }
}

// ---------------- fused single-pass online-softmax attention -------------------
__device__ __forceinline__ void store_split4(int d, int col0, float4 r) {
    __nv_bfloat16 h0 = __float2bfloat16(r.x);
    __nv_bfloat16 h1 = __float2bfloat16(r.y);
    __nv_bfloat16 h2 = __float2bfloat16(r.z);
    __nv_bfloat16 h3 = __float2bfloat16(r.w);
    __nv_bfloat162* dh = (__nv_bfloat162*)(g_ahi + (size_t)d * DD + col0);
    dh[0] = __halves2bfloat162(h0, h1);
    dh[1] = __halves2bfloat162(h2, h3);
    __nv_bfloat162* dl = (__nv_bfloat162*)(g_alo + (size_t)d * DD + col0);
    dl[0] = __halves2bfloat162(__float2bfloat16(r.x - __bfloat162float(h0)),
                               __float2bfloat16(r.y - __bfloat162float(h1)));
    dl[1] = __halves2bfloat162(__float2bfloat16(r.z - __bfloat162float(h2)),
                               __float2bfloat16(r.w - __bfloat162float(h3)));
}

// mode 1: intermediate layer -> relu + bf16 split store; mode 0: final -> fp32 out
__global__ __launch_bounds__(256) void dst_attn_kernel(float* __restrict__ out, int mode) {
    int d = (blockIdx.x * blockDim.x + threadIdx.x) >> 5;
    int lane = threadIdx.x & 31;
    if (d >= NN) return;

    int beg = g_off[d];
    int deg = g_off[d + 1] - beg;

    const float4* q4 = (const float4*)(g_q + (size_t)d * DD);
    float4 qa = q4[lane], qb = q4[lane + 32];

    float m = -INFINITY, den = 0.f;
    float4 acca = make_float4(0.f, 0.f, 0.f, 0.f);
    float4 accb = make_float4(0.f, 0.f, 0.f, 0.f);

    #pragma unroll 2
    for (int j = 0; j < deg; j++) {
        int s = __ldg(&g_esrc[beg + j]);
        const float4* k4 = (const float4*)(g_k + (size_t)s * DD);
        const float4* v4 = (const float4*)(g_v + (size_t)s * DD);
        // issue all 4 gathers before the reduce chain
        float4 ka = __ldg(&k4[lane]);
        float4 kb = __ldg(&k4[lane + 32]);
        float4 va = __ldg(&v4[lane]);
        float4 vb = __ldg(&v4[lane + 32]);

        float p = qa.x * ka.x + qa.y * ka.y + qa.z * ka.z + qa.w * ka.w
                + qb.x * kb.x + qb.y * kb.y + qb.z * kb.z + qb.w * kb.w;
        #pragma unroll
        for (int o = 16; o; o >>= 1) p += __shfl_xor_sync(0xffffffffu, p, o);
        p *= 0.0625f;  // 1/sqrt(256)

        float mn = fmaxf(m, p);
        float scale = __expf(m - mn);   // m=-inf first iter -> scale=0
        float w = __expf(p - mn);
        den = den * scale + w;
        m = mn;
        acca.x = acca.x * scale + w * va.x;
        acca.y = acca.y * scale + w * va.y;
        acca.z = acca.z * scale + w * va.z;
        acca.w = acca.w * scale + w * va.w;
        accb.x = accb.x * scale + w * vb.x;
        accb.y = accb.y * scale + w * vb.y;
        accb.z = accb.z * scale + w * vb.z;
        accb.w = accb.w * scale + w * vb.w;
    }

    float invden = 1.0f / (den + 1e-16f);

    const float4* s4 = (const float4*)(g_s + (size_t)d * DD);
    float4 sa = s4[lane], sb = s4[lane + 32];
    float4 oa, ob;
    oa.x = acca.x * invden + sa.x; oa.y = acca.y * invden + sa.y;
    oa.z = acca.z * invden + sa.z; oa.w = acca.w * invden + sa.w;
    ob.x = accb.x * invden + sb.x; ob.y = accb.y * invden + sb.y;
    ob.z = accb.z * invden + sb.z; ob.w = accb.w * invden + sb.w;

    if (mode) {
        oa.x = fmaxf(oa.x, 0.f); oa.y = fmaxf(oa.y, 0.f);
        oa.z = fmaxf(oa.z, 0.f); oa.w = fmaxf(oa.w, 0.f);
        ob.x = fmaxf(ob.x, 0.f); ob.y = fmaxf(ob.y, 0.f);
        ob.z = fmaxf(ob.z, 0.f); ob.w = fmaxf(ob.w, 0.f);
        store_split4(d, lane * 4, oa);
        store_split4(d, 128 + lane * 4, ob);
    } else {
        float4* o4 = (float4*)(out + (size_t)d * DD);
        o4[lane] = oa;
        o4[lane + 32] = ob;
    }
}

// ---------------- launch --------------------------------------------------------
extern "C" void kernel_launch(void* const* d_in, const int* in_sizes, int n_in,
                              void* d_out, int out_size) {
    const float* x  = (const float*)d_in[0];
    const int*   ei = (const int*)d_in[1];
    const float* Wq = (const float*)d_in[2];
    const float* bq = (const float*)d_in[3];
    const float* Wk = (const float*)d_in[4];
    const float* bk = (const float*)d_in[5];
    const float* Wv = (const float*)d_in[6];
    const float* bv = (const float*)d_in[7];
    const float* Ws = (const float*)d_in[8];
    const float* bs = (const float*)d_in[9];
    float* out = (float*)d_out;

    cudaFuncSetAttribute(bf16x3_gemm_kernel,
                         cudaFuncAttributeMaxDynamicSharedMemorySize, GEMM_SMEM);

    int split_blocks = (NN * DD / 4 + 255) / 256;
    asplit_kernel<<<split_blocks, 256>>>(x);            // layer-0 input split
    wsplit_kernel<<<dim3(8, 8, 12), dim3(32, 8)>>>(Wq, Wk, Wv, Ws);

    detect_idx_kernel<<<1, 32>>>(ei);
    zero_deg_kernel<<<(NN + 255) / 256, 256>>>();
    convert_hist_kernel<<<(EE + 255) / 256, 256>>>(ei);
    scan1_kernel<<<SCAN_NB, 256>>>();
    scan2_kernel<<<1, 256>>>();
    scan3_kernel<<<SCAN_NB, 256>>>();
    scatter_kernel<<<(EE + 255) / 256, 256>>>();

    dim3 ggrid((NN + 127) / 128, 2, 4);
    int attn_blocks = (NN * 32 + 255) / 256;

    for (int l = 0; l < LL; l++) {
        size_t bo = (size_t)l * DD;
        bf16x3_gemm_kernel<<<ggrid, 256, GEMM_SMEM>>>(
            l, bq + bo, bk + bo, bv + bo, bs + bo, NN);
        dst_attn_kernel<<<attn_blocks, 256>>>(out, (l < LL - 1) ? 1 : 0);
    }
}

// round 17
// speedup vs baseline: 1.3327x; 1.2195x over previous
#include <cuda_runtime.h>
#include <cuda_bf16.h>
#include <cuda_fp16.h>
#include <mma.h>
#include <math.h>
#include <stdint.h>

using namespace nvcuda;

#define NN 50000
#define DD 256
#define EE 800000
#define LL 3

// ---------------- device scratch ---------------------------------------------
__device__ float g_q[NN * DD];
__device__ float g_s[NN * DD];
__device__ __half g_kh[NN * DD];                 // fp16 K for gathers
__device__ __half g_vh[NN * DD];                 // fp16 V for gathers
__device__ __nv_bfloat16 g_ahi[NN * DD];         // layer input, bf16-split
__device__ __nv_bfloat16 g_alo[NN * DD];
__device__ __nv_bfloat16 g_wthi[12 * DD * DD];   // [mat][n][k] transposed + split
__device__ __nv_bfloat16 g_wtlo[12 * DD * DD];
__device__ int   g_src[EE];
__device__ int   g_dst[EE];
__device__ int   g_esrc[EE];
__device__ int   g_deg[NN];
__device__ int   g_off[NN + 1];
__device__ int   g_bsum[256];
__device__ int   g_is64;

// ---------------- cp.async helpers --------------------------------------------
__device__ __forceinline__ void cp_async16(uint32_t dst, const void* src) {
    asm volatile("cp.async.cg.shared.global [%0], [%1], 16;" :: "r"(dst), "l"(src));
}
__device__ __forceinline__ void cp_commit() {
    asm volatile("cp.async.commit_group;" ::: "memory");
}
template <int N>
__device__ __forceinline__ void cp_wait() {
    asm volatile("cp.async.wait_group %0;" :: "n"(N) : "memory");
}

// ---------------- edge-index dtype detection + CSR -----------------------------
__global__ void detect_idx_kernel(const int* __restrict__ ei) {
    if (threadIdx.x == 0 && blockIdx.x == 0) {
        int all_hi_zero = 1;
        for (int j = 0; j < 256; j++)
            if (ei[2 * j + 1] != 0) { all_hi_zero = 0; break; }
        g_is64 = all_hi_zero;
    }
}
__global__ void zero_deg_kernel() {
    int i = blockIdx.x * blockDim.x + threadIdx.x;
    if (i < NN) g_deg[i] = 0;
}
__global__ void convert_hist_kernel(const int* __restrict__ ei) {
    int i = blockIdx.x * blockDim.x + threadIdx.x;
    if (i >= EE) return;
    int s, d;
    if (g_is64) { s = ei[2 * i]; d = ei[2 * (EE + i)]; }
    else        { s = ei[i];     d = ei[EE + i]; }
    g_src[i] = s; g_dst[i] = d;
    atomicAdd(&g_deg[d], 1);
}
#define SCAN_NB 196
__global__ __launch_bounds__(256) void scan1_kernel() {
    __shared__ int sh[256];
    int i = blockIdx.x * 256 + threadIdx.x;
    int v = (i < NN) ? g_deg[i] : 0;
    sh[threadIdx.x] = v;
    __syncthreads();
    for (int o = 128; o; o >>= 1) {
        if (threadIdx.x < o) sh[threadIdx.x] += sh[threadIdx.x + o];
        __syncthreads();
    }
    if (threadIdx.x == 0) g_bsum[blockIdx.x] = sh[0];
}
__global__ __launch_bounds__(256) void scan2_kernel() {
    __shared__ int sh[256];
    int t = threadIdx.x;
    sh[t] = (t < SCAN_NB) ? g_bsum[t] : 0;
    __syncthreads();
    for (int o = 1; o < 256; o <<= 1) {
        int v = (t >= o) ? sh[t - o] : 0;
        __syncthreads();
        sh[t] += v;
        __syncthreads();
    }
    if (t < SCAN_NB) g_bsum[t] = (t == 0) ? 0 : sh[t - 1];
    if (t == 0) g_off[NN] = EE;
}
__global__ __launch_bounds__(256) void scan3_kernel() {
    __shared__ int sh[256];
    int i = blockIdx.x * 256 + threadIdx.x;
    int t = threadIdx.x;
    int v = (i < NN) ? g_deg[i] : 0;
    sh[t] = v;
    __syncthreads();
    for (int o = 1; o < 256; o <<= 1) {
        int u = (t >= o) ? sh[t - o] : 0;
        __syncthreads();
        sh[t] += u;
        __syncthreads();
    }
    if (i < NN) {
        g_off[i] = g_bsum[blockIdx.x] + sh[t] - v;
        g_deg[i] = 0;
    }
}
__global__ void scatter_kernel() {
    int i = blockIdx.x * blockDim.x + threadIdx.x;
    if (i >= EE) return;
    int d = g_dst[i];
    int pos = g_off[d] + atomicAdd(&g_deg[d], 1);
    g_esrc[pos] = g_src[i];
}

// ---------------- weight transpose + bf16 split --------------------------------
__global__ __launch_bounds__(256) void wsplit_kernel(
    const float* __restrict__ Wq, const float* __restrict__ Wk,
    const float* __restrict__ Wv, const float* __restrict__ Ws)
{
    __shared__ float t[32][33];
    int m = blockIdx.z;
    int l = m >> 2, wi = m & 3;
    const float* W = ((wi == 0) ? Wq : (wi == 1) ? Wk : (wi == 2) ? Wv : Ws) + (size_t)l * DD * DD;
    int k0 = blockIdx.y * 32, n0 = blockIdx.x * 32;
    #pragma unroll
    for (int r = 0; r < 32; r += 8) {
        int k = k0 + threadIdx.y + r, n = n0 + threadIdx.x;
        t[threadIdx.y + r][threadIdx.x] = W[k * DD + n];
    }
    __syncthreads();
    __nv_bfloat16* ohi = g_wthi + (size_t)m * DD * DD;
    __nv_bfloat16* olo = g_wtlo + (size_t)m * DD * DD;
    #pragma unroll
    for (int r = 0; r < 32; r += 8) {
        int n = n0 + threadIdx.y + r, k = k0 + threadIdx.x;
        float x = t[threadIdx.x][threadIdx.y + r];
        __nv_bfloat16 hi = __float2bfloat16(x);
        __nv_bfloat16 lo = __float2bfloat16(x - __bfloat162float(hi));
        ohi[n * DD + k] = hi;
        olo[n * DD + k] = lo;
    }
}

// ---------------- A split for the layer-0 input x ------------------------------
__global__ __launch_bounds__(256) void asplit_kernel(const float* __restrict__ A) {
    int i = blockIdx.x * blockDim.x + threadIdx.x;   // float4 index
    if (i >= NN * DD / 4) return;
    float4 av = __ldg((const float4*)A + i);
    __nv_bfloat16 h0 = __float2bfloat16(av.x);
    __nv_bfloat16 h1 = __float2bfloat16(av.y);
    __nv_bfloat16 h2 = __float2bfloat16(av.z);
    __nv_bfloat16 h3 = __float2bfloat16(av.w);
    __nv_bfloat162 hl = __halves2bfloat162(h0, h1);
    __nv_bfloat162 hh = __halves2bfloat162(h2, h3);
    __nv_bfloat162 ll = __halves2bfloat162(
        __float2bfloat16(av.x - __bfloat162float(h0)),
        __float2bfloat16(av.y - __bfloat162float(h1)));
    __nv_bfloat162 lh = __halves2bfloat162(
        __float2bfloat16(av.z - __bfloat162float(h2)),
        __float2bfloat16(av.w - __bfloat162float(h3)));
    ((__nv_bfloat162*)g_ahi)[i * 2]     = hl;
    ((__nv_bfloat162*)g_ahi)[i * 2 + 1] = hh;
    ((__nv_bfloat162*)g_alo)[i * 2]     = ll;
    ((__nv_bfloat162*)g_alo)[i * 2 + 1] = lh;
}

// ---------------- bf16x3 WMMA GEMM (R11 config: 128x128, 2 CTA/SM) -------------
// z: 0=q (fp32), 1=k (fp16), 2=v (fp16), 3=s (fp32)
#define APITCH 40                       // bf16 elems; 80B pitch (16B-aligned rows)
#define TILE_SPLIT_B (128 * APITCH * 2) // 10240 bytes per split
#define STAGE_B (4 * TILE_SPLIT_B)      // 40960
#define GEMM_SMEM (2 * STAGE_B)         // 81920 -> 2 CTAs/SM

__global__ __launch_bounds__(256, 2) void bf16x3_gemm_kernel(
    int layer,
    const float* __restrict__ bq, const float* __restrict__ bk,
    const float* __restrict__ bv, const float* __restrict__ bs, int M)
{
    extern __shared__ char smem[];
    const int tid = threadIdx.x;
    const int wid = tid >> 5;
    const int wm = wid >> 2;          // 0..1
    const int wn = wid & 3;           // 0..3
    const int bm = blockIdx.x * 128;
    const int bn = blockIdx.y * 128;
    const int z  = blockIdx.z;

    const int mat = layer * 4 + z;
    const __nv_bfloat16* Whi = g_wthi + (size_t)mat * DD * DD;
    const __nv_bfloat16* Wlo = g_wtlo + (size_t)mat * DD * DD;

    const uint32_t smem_base = (uint32_t)__cvta_generic_to_shared(smem);

    wmma::fragment<wmma::accumulator, 16, 16, 16, float> c[4][2];
    #pragma unroll
    for (int i = 0; i < 4; i++)
        #pragma unroll
        for (int j = 0; j < 2; j++) wmma::fill_fragment(c[i][j], 0.f);

    auto load_chunk = [&](int ck, int buf) {
        uint32_t sb = smem_base + buf * STAGE_B;
        #pragma unroll
        for (int it = 0; it < 8; it++) {
            int seg = tid + it * 256;          // 0..2047
            int split = seg >> 9;              // 0=Ahi 1=Alo 2=Bhi 3=Blo
            int rem = seg & 511;
            int row = rem >> 2;                // 0..127
            int s4  = rem & 3;                 // 16B seg within 64B row
            uint32_t daddr = sb + split * TILE_SPLIT_B + (row * APITCH + s4 * 8) * 2;
            const __nv_bfloat16* gp;
            if (split == 0) {
                int gr = min(bm + row, M - 1);
                gp = g_ahi + (size_t)gr * DD + ck * 32 + s4 * 8;
            } else if (split == 1) {
                int gr = min(bm + row, M - 1);
                gp = g_alo + (size_t)gr * DD + ck * 32 + s4 * 8;
            } else if (split == 2) {
                gp = Whi + (size_t)(bn + row) * DD + ck * 32 + s4 * 8;
            } else {
                gp = Wlo + (size_t)(bn + row) * DD + ck * 32 + s4 * 8;
            }
            cp_async16(daddr, gp);
        }
        cp_commit();
    };

    load_chunk(0, 0);

    for (int ck = 0; ck < 8; ck++) {
        if (ck < 7) { load_chunk(ck + 1, (ck + 1) & 1); cp_wait<1>(); }
        else { cp_wait<0>(); }
        __syncthreads();

        char* stg = smem + (ck & 1) * STAGE_B;
        __nv_bfloat16* Ahi = (__nv_bfloat16*)(stg);
        __nv_bfloat16* Alo = (__nv_bfloat16*)(stg + TILE_SPLIT_B);
        __nv_bfloat16* Bhi = (__nv_bfloat16*)(stg + 2 * TILE_SPLIT_B);
        __nv_bfloat16* Blo = (__nv_bfloat16*)(stg + 3 * TILE_SPLIT_B);

        #pragma unroll
        for (int kk = 0; kk < 2; kk++) {
            wmma::fragment<wmma::matrix_b, 16, 16, 16, __nv_bfloat16, wmma::col_major> bH[2], bL[2];
            #pragma unroll
            for (int j = 0; j < 2; j++) {
                wmma::load_matrix_sync(bH[j], Bhi + (wn * 32 + j * 16) * APITCH + kk * 16, APITCH);
                wmma::load_matrix_sync(bL[j], Blo + (wn * 32 + j * 16) * APITCH + kk * 16, APITCH);
            }
            {
                wmma::fragment<wmma::matrix_a, 16, 16, 16, __nv_bfloat16, wmma::row_major> aH[4];
                #pragma unroll
                for (int i = 0; i < 4; i++)
                    wmma::load_matrix_sync(aH[i], Ahi + (wm * 64 + i * 16) * APITCH + kk * 16, APITCH);
                #pragma unroll
                for (int i = 0; i < 4; i++)
                    #pragma unroll
                    for (int j = 0; j < 2; j++) {
                        wmma::mma_sync(c[i][j], aH[i], bH[j], c[i][j]);
                        wmma::mma_sync(c[i][j], aH[i], bL[j], c[i][j]);
                    }
            }
            {
                wmma::fragment<wmma::matrix_a, 16, 16, 16, __nv_bfloat16, wmma::row_major> aL[4];
                #pragma unroll
                for (int i = 0; i < 4; i++)
                    wmma::load_matrix_sync(aL[i], Alo + (wm * 64 + i * 16) * APITCH + kk * 16, APITCH);
                #pragma unroll
                for (int i = 0; i < 4; i++)
                    #pragma unroll
                    for (int j = 0; j < 2; j++)
                        wmma::mma_sync(c[i][j], aL[i], bH[j], c[i][j]);
            }
        }
        __syncthreads();
    }

    // epilogue: stage accumulators, coalesced store + bias
    float* stage = (float*)smem;   // 128 x 132
    #pragma unroll
    for (int i = 0; i < 4; i++)
        #pragma unroll
        for (int j = 0; j < 2; j++)
            wmma::store_matrix_sync(stage + (wm * 64 + i * 16) * 132 + wn * 32 + j * 16,
                                    c[i][j], 132, wmma::mem_row_major);
    __syncthreads();

    const float* bias = ((z == 0) ? bq : (z == 1) ? bk : (z == 2) ? bv : bs);

    #pragma unroll
    for (int it = 0; it < 16; it++) {
        int idx = tid + it * 256;
        int row = idx >> 5, c4 = idx & 31;
        int gr = bm + row;
        if (gr < M) {
            float4 vv = *(float4*)(stage + row * 132 + c4 * 4);
            float4 bb = __ldg((const float4*)(bias + bn + c4 * 4));
            vv.x += bb.x; vv.y += bb.y; vv.z += bb.z; vv.w += bb.w;
            size_t off = (size_t)gr * DD + bn + c4 * 4;
            if (z == 0) {
                *(float4*)(g_q + off) = vv;
            } else if (z == 3) {
                *(float4*)(g_s + off) = vv;
            } else {
                // k and v: store fp16 (attention gathers these)
                union { __half2 h[2]; uint2 u; } pk;
                pk.h[0] = __floats2half2_rn(vv.x, vv.y);
                pk.h[1] = __floats2half2_rn(vv.z, vv.w);
                __half* hp = (z == 1) ? g_kh : g_vh;
                *(uint2*)(hp + off) = pk.u;
            }
        }
    }
}

// ---------------- fused single-pass online-softmax attention (fp16 K/V) --------
__device__ __forceinline__ void store_split4(int d, int col0, float4 r) {
    __nv_bfloat16 h0 = __float2bfloat16(r.x);
    __nv_bfloat16 h1 = __float2bfloat16(r.y);
    __nv_bfloat16 h2 = __float2bfloat16(r.z);
    __nv_bfloat16 h3 = __float2bfloat16(r.w);
    __nv_bfloat162* dh = (__nv_bfloat162*)(g_ahi + (size_t)d * DD + col0);
    dh[0] = __halves2bfloat162(h0, h1);
    dh[1] = __halves2bfloat162(h2, h3);
    __nv_bfloat162* dl = (__nv_bfloat162*)(g_alo + (size_t)d * DD + col0);
    dl[0] = __halves2bfloat162(__float2bfloat16(r.x - __bfloat162float(h0)),
                               __float2bfloat16(r.y - __bfloat162float(h1)));
    dl[1] = __halves2bfloat162(__float2bfloat16(r.z - __bfloat162float(h2)),
                               __float2bfloat16(r.w - __bfloat162float(h3)));
}

// mode 1: intermediate layer -> relu + bf16 split store; mode 0: final -> fp32 out
__global__ __launch_bounds__(256) void dst_attn_kernel(float* __restrict__ out, int mode) {
    int d = (blockIdx.x * blockDim.x + threadIdx.x) >> 5;
    int lane = threadIdx.x & 31;
    if (d >= NN) return;

    int beg = g_off[d];
    int deg = g_off[d + 1] - beg;

    // lane covers columns [lane*8, lane*8+8)
    const float4* q4 = (const float4*)(g_q + (size_t)d * DD);
    float4 q0 = q4[lane * 2], q1 = q4[lane * 2 + 1];

    float m = -INFINITY, den = 0.f;
    float acc[8];
    #pragma unroll
    for (int i = 0; i < 8; i++) acc[i] = 0.f;

    #pragma unroll 2
    for (int j = 0; j < deg; j++) {
        int s = __ldg(&g_esrc[beg + j]);
        // one 16B load each for K and V (8 halves)
        uint4 kw = __ldg((const uint4*)(g_kh + (size_t)s * DD) + lane);
        uint4 vw = __ldg((const uint4*)(g_vh + (size_t)s * DD) + lane);

        float2 k0 = __half22float2(*(__half2*)&kw.x);
        float2 k1 = __half22float2(*(__half2*)&kw.y);
        float2 k2 = __half22float2(*(__half2*)&kw.z);
        float2 k3 = __half22float2(*(__half2*)&kw.w);

        float p = q0.x * k0.x + q0.y * k0.y + q0.z * k1.x + q0.w * k1.y
                + q1.x * k2.x + q1.y * k2.y + q1.z * k3.x + q1.w * k3.y;
        #pragma unroll
        for (int o = 16; o; o >>= 1) p += __shfl_xor_sync(0xffffffffu, p, o);
        p *= 0.0625f;  // 1/sqrt(256)

        float mn = fmaxf(m, p);
        float scale = __expf(m - mn);   // m=-inf first iter -> scale=0
        float w = __expf(p - mn);
        den = den * scale + w;
        m = mn;

        float2 v0 = __half22float2(*(__half2*)&vw.x);
        float2 v1 = __half22float2(*(__half2*)&vw.y);
        float2 v2 = __half22float2(*(__half2*)&vw.z);
        float2 v3 = __half22float2(*(__half2*)&vw.w);
        acc[0] = acc[0] * scale + w * v0.x;
        acc[1] = acc[1] * scale + w * v0.y;
        acc[2] = acc[2] * scale + w * v1.x;
        acc[3] = acc[3] * scale + w * v1.y;
        acc[4] = acc[4] * scale + w * v2.x;
        acc[5] = acc[5] * scale + w * v2.y;
        acc[6] = acc[6] * scale + w * v3.x;
        acc[7] = acc[7] * scale + w * v3.y;
    }

    float invden = 1.0f / (den + 1e-16f);

    const float4* s4 = (const float4*)(g_s + (size_t)d * DD);
    float4 sa = s4[lane * 2], sb = s4[lane * 2 + 1];
    float4 oa, ob;
    oa.x = acc[0] * invden + sa.x; oa.y = acc[1] * invden + sa.y;
    oa.z = acc[2] * invden + sa.z; oa.w = acc[3] * invden + sa.w;
    ob.x = acc[4] * invden + sb.x; ob.y = acc[5] * invden + sb.y;
    ob.z = acc[6] * invden + sb.z; ob.w = acc[7] * invden + sb.w;

    if (mode) {
        oa.x = fmaxf(oa.x, 0.f); oa.y = fmaxf(oa.y, 0.f);
        oa.z = fmaxf(oa.z, 0.f); oa.w = fmaxf(oa.w, 0.f);
        ob.x = fmaxf(ob.x, 0.f); ob.y = fmaxf(ob.y, 0.f);
        ob.z = fmaxf(ob.z, 0.f); ob.w = fmaxf(ob.w, 0.f);
        store_split4(d, lane * 8, oa);
        store_split4(d, lane * 8 + 4, ob);
    } else {
        float4* o4 = (float4*)(out + (size_t)d * DD);
        o4[lane * 2] = oa;
        o4[lane * 2 + 1] = ob;
    }
}

// ---------------- launch --------------------------------------------------------
extern "C" void kernel_launch(void* const* d_in, const int* in_sizes, int n_in,
                              void* d_out, int out_size) {
    const float* x  = (const float*)d_in[0];
    const int*   ei = (const int*)d_in[1];
    const float* Wq = (const float*)d_in[2];
    const float* bq = (const float*)d_in[3];
    const float* Wk = (const float*)d_in[4];
    const float* bk = (const float*)d_in[5];
    const float* Wv = (const float*)d_in[6];
    const float* bv = (const float*)d_in[7];
    const float* Ws = (const float*)d_in[8];
    const float* bs = (const float*)d_in[9];
    float* out = (float*)d_out;

    cudaFuncSetAttribute(bf16x3_gemm_kernel,
                         cudaFuncAttributeMaxDynamicSharedMemorySize, GEMM_SMEM);

    int split_blocks = (NN * DD / 4 + 255) / 256;
    asplit_kernel<<<split_blocks, 256>>>(x);            // layer-0 input split
    wsplit_kernel<<<dim3(8, 8, 12), dim3(32, 8)>>>(Wq, Wk, Wv, Ws);

    detect_idx_kernel<<<1, 32>>>(ei);
    zero_deg_kernel<<<(NN + 255) / 256, 256>>>();
    convert_hist_kernel<<<(EE + 255) / 256, 256>>>(ei);
    scan1_kernel<<<SCAN_NB, 256>>>();
    scan2_kernel<<<1, 256>>>();
    scan3_kernel<<<SCAN_NB, 256>>>();
    scatter_kernel<<<(EE + 255) / 256, 256>>>();

    dim3 ggrid((NN + 127) / 128, 2, 4);
    int attn_blocks = (NN * 32 + 255) / 256;

    for (int l = 0; l < LL; l++) {
        size_t bo = (size_t)l * DD;
        bf16x3_gemm_kernel<<<ggrid, 256, GEMM_SMEM>>>(
            l, bq + bo, bk + bo, bv + bo, bs + bo, NN);
        dst_attn_kernel<<<attn_blocks, 256>>>(out, (l < LL - 1) ? 1 : 0);
    }
}